// round 8
// baseline (speedup 1.0000x reference)
#include <cuda_runtime.h>
#include <math_constants.h>

#define BB 512
#define TT 512
#define KK 64

// 16.7 MB history scratch (argmax index per (b, t, j)), plus per-batch best-last tag.
__device__ unsigned char g_hist[(size_t)BB * TT * KK];
__device__ int g_best[BB];

// ---------------------------------------------------------------------------
// Packed f32x2 helpers. Each half computes the same fl(a+b) as scalar FADD.rn
// -> bit-exact vs reference association (s + t) + e.
// ---------------------------------------------------------------------------
__device__ __forceinline__ unsigned long long addx2(unsigned long long a,
                                                    unsigned long long b) {
    unsigned long long r;
    asm("add.rn.f32x2 %0, %1, %2;" : "=l"(r) : "l"(a), "l"(b));
    return r;
}
__device__ __forceinline__ unsigned long long packf2(float lo, float hi) {
    unsigned long long r;
    asm("mov.b64 %0, {%1, %2};" : "=l"(r) : "f"(lo), "f"(hi));
    return r;
}
__device__ __forceinline__ void unpackf2(unsigned long long v, float& lo, float& hi) {
    asm("mov.b64 {%0, %1}, %2;" : "=f"(lo), "=f"(hi) : "l"(v));
}

// Warp-wide f32 max: 5-level shfl butterfly (redux.f32 not supported on sm_103).
__device__ __forceinline__ float warp_max_f32(float v) {
#pragma unroll
    for (int d = 16; d; d >>= 1)
        v = fmaxf(v, __shfl_xor_sync(0xFFFFFFFFu, v, d));
    return v;
}

// ---------------------------------------------------------------------------
// Forward Viterbi, one WARP per batch. Lane l owns next-tags j0=l, j1=l+32.
// Scores in registers (shfl broadcast). Live prev-tag set = 2 ballot masks.
// Exact pruning: i prunable iff s_i < smax + (Tmin - Tmax) - 0.05; margin >>
// float rounding, so pruned i can never be the argmax (not even via ties).
// Argmax per j: one ascending strict-> chain per mask, merged mask0-preferred
// (all mask0 indices < mask1 indices) -> exact jnp.argmax first-index ties.
// ---------------------------------------------------------------------------
__global__ __launch_bounds__(128) void viterbi_forward(
    const float* __restrict__ emissions,   // [B, T, K]
    const int*   __restrict__ mask,        // [B, T]
    const float* __restrict__ start_t,     // [K]
    const float* __restrict__ end_t,       // [K]
    const float* __restrict__ trans)       // [K, K]
{
    const int tid  = threadIdx.x;
    const int lane = tid & 31;
    const int w    = tid >> 5;
    const int b    = blockIdx.x * 4 + w;

    // tp_sh[i][l] = (trans[i][l], trans[i][l+32]) -> one LDS.64 per candidate.
    __shared__ __align__(16) float2 tp_sh[KK][32];
    __shared__ float red_sh[8];

    // ---- one-time: stage trans, compute global Tmin/Tmax ----
    float tmn = CUDART_INF_F, tmx = -CUDART_INF_F;
    for (int i = w; i < KK; i += 4) {
        const float a = trans[i * KK + lane];
        const float c = trans[i * KK + 32 + lane];
        tp_sh[i][lane] = make_float2(a, c);
        tmn = fminf(tmn, fminf(a, c));
        tmx = fmaxf(tmx, fmaxf(a, c));
    }
#pragma unroll
    for (int d = 16; d; d >>= 1) {
        tmn = fminf(tmn, __shfl_xor_sync(0xFFFFFFFFu, tmn, d));
        tmx = fmaxf(tmx, __shfl_xor_sync(0xFFFFFFFFu, tmx, d));
    }
    if (lane == 0) { red_sh[w] = tmn; red_sh[4 + w] = tmx; }
    __syncthreads();
    const float mn = fminf(fminf(red_sh[0], red_sh[1]), fminf(red_sh[2], red_sh[3]));
    const float mx = fmaxf(fmaxf(red_sh[4], red_sh[5]), fmaxf(red_sh[6], red_sh[7]));
    const float thrD = (mn - mx) - 0.05f;

    const float* em = emissions + (size_t)b * TT * KK;
    const int*   mk = mask + (size_t)b * TT;

    // ---- init scores (t = 0) ----
    float s0 = start_t[lane]      + em[lane];
    float s1 = start_t[lane + 32] + em[lane + 32];

    // ---- initial live masks ----
    unsigned mask0, mask1;
    {
        const float thr = warp_max_f32(fmaxf(s0, s1)) + thrD;
        mask0 = __ballot_sync(0xFFFFFFFFu, s0 >= thr);
        mask1 = __ballot_sync(0xFFFFFFFFu, s1 >= thr);
    }

    // ---- prefetch (depth 2): emissions + mask ----
    float e0c = em[KK + lane],      e1c = em[KK + 32 + lane];
    float e0n = em[2 * KK + lane],  e1n = em[2 * KK + 32 + lane];
    int   mc  = mk[1];
    int   mnx = mk[2];

    unsigned char* hp = g_hist + ((size_t)b * TT + 1) * KK;

    for (int t = 1; t < TT; ++t) {
        // branch-free prefetch of step t+2 (clamped at tail)
        const int tpf = (t + 2 < TT) ? (t + 2) : (TT - 1);
        const float e0p = em[tpf * KK + lane];
        const float e1p = em[tpf * KK + 32 + lane];
        const int   mpf = mk[tpf];

        const unsigned long long ex = packf2(e0c, e1c);

        // ---- argmax over live prev-tags: 2 chains per j (mask0 / mask1) ----
        float bA0 = -CUDART_INF_F, bA1 = -CUDART_INF_F;   // from mask0
        int   iA0 = 0,             iA1 = 0;
        float bC0 = -CUDART_INF_F, bC1 = -CUDART_INF_F;   // from mask1
        int   iC0 = 32,            iC1 = 32;

        unsigned m0 = mask0;           // uniform across warp
        while (m0) {
            const int i = __ffs(m0) - 1;
            m0 &= m0 - 1;
            const float si = __shfl_sync(0xFFFFFFFFu, s0, i);
            const unsigned long long tp =
                *reinterpret_cast<const unsigned long long*>(&tp_sh[i][lane]);
            const unsigned long long v2 = addx2(addx2(packf2(si, si), tp), ex);
            float v0, v1; unpackf2(v2, v0, v1);
            const bool g0 = v0 > bA0;
            bA0 = g0 ? v0 : bA0;  iA0 = g0 ? i : iA0;
            const bool g1 = v1 > bA1;
            bA1 = g1 ? v1 : bA1;  iA1 = g1 ? i : iA1;
        }
        unsigned m1 = mask1;
        while (m1) {
            const int i = __ffs(m1) - 1;
            m1 &= m1 - 1;
            const float si = __shfl_sync(0xFFFFFFFFu, s1, i);
            const unsigned long long tp =
                *reinterpret_cast<const unsigned long long*>(&tp_sh[i + 32][lane]);
            const unsigned long long v2 = addx2(addx2(packf2(si, si), tp), ex);
            float v0, v1; unpackf2(v2, v0, v1);
            const bool g0 = v0 > bC0;
            bC0 = g0 ? v0 : bC0;  iC0 = g0 ? (i + 32) : iC0;
            const bool g1 = v1 > bC1;
            bC1 = g1 ? v1 : bC1;  iC1 = g1 ? (i + 32) : iC1;
        }

        // merge: mask0 chain preferred on ties (its indices are all smaller)
        const bool h0 = bC0 > bA0;
        const float bst0 = h0 ? bC0 : bA0;
        const int   bid0 = h0 ? iC0 : iA0;
        const bool h1 = bC1 > bA1;
        const float bst1 = h1 ? bC1 : bA1;
        const int   bid1 = h1 ? iC1 : iA1;

        // history always records the argmax; mask only gates the score.
        hp[lane]      = (unsigned char)bid0;
        hp[lane + 32] = (unsigned char)bid1;

        s0 = mc ? bst0 : s0;
        s1 = mc ? bst1 : s1;

        // ---- threshold + live masks for next step ----
        const float thr = warp_max_f32(fmaxf(s0, s1)) + thrD;
        mask0 = __ballot_sync(0xFFFFFFFFu, s0 >= thr);
        mask1 = __ballot_sync(0xFFFFFFFFu, s1 >= thr);

        hp += KK;
        e0c = e0n; e1c = e1n; e0n = e0p; e1n = e1p;
        mc  = mnx; mnx = mpf;
    }

    // ---- final: + end_transitions, first-index argmax over all 64 tags ----
    {
        const float v0 = s0 + end_t[lane];
        const float v1 = s1 + end_t[lane + 32];
        float bv; int bi;
        if (v1 > v0) { bv = v1; bi = lane + 32; }
        else         { bv = v0; bi = lane; }
#pragma unroll
        for (int d = 16; d; d >>= 1) {
            const float vo = __shfl_xor_sync(0xFFFFFFFFu, bv, d);
            const int   io = __shfl_xor_sync(0xFFFFFFFFu, bi, d);
            if (vo > bv || (vo == bv && io < bi)) { bv = vo; bi = io; }
        }
        if (lane == 0) g_best[b] = bi;
    }
}

// ---------------------------------------------------------------------------
// Backtrace: one block per batch. Stage the 32KB history slab + mask into
// shared, then one thread walks the dependent chain at LDS latency.
// Output tags written as FLOAT32 (harness output dtype).
// ---------------------------------------------------------------------------
__global__ __launch_bounds__(256) void viterbi_backtrace(
    const int*  __restrict__ mask,   // [B, T]
    float*      __restrict__ out)    // [B, T] float32 tags
{
    const int b = blockIdx.x;
    __shared__ unsigned char h[TT * KK];   // 32 KB
    __shared__ int msk[TT];                // 2 KB

    const uint4* src = (const uint4*)(g_hist + (size_t)b * TT * KK);
    uint4* dst = (uint4*)h;
#pragma unroll 4
    for (int k = threadIdx.x; k < (TT * KK) / 16; k += blockDim.x)
        dst[k] = src[k];
    for (int t = threadIdx.x; t < TT; t += blockDim.x)
        msk[t] = mask[b * TT + t];
    __syncthreads();

    if (threadIdx.x == 0) {
        int tag = g_best[b];
        out[b * TT + (TT - 1)] = (float)tag;
        for (int t = TT - 1; t >= 1; --t) {
            const int prev = h[t * KK + tag];
            tag = msk[t] ? prev : tag;
            out[b * TT + t - 1] = (float)tag;
        }
    }
}

// No-op kernel: pads the per-replay launch cycle to 5 so ncu's "-s 5 -c 1"
// capture lands on viterbi_forward (launch #6) instead of the backtrace.
__global__ void profiling_pad_kernel() {}

extern "C" void kernel_launch(void* const* d_in, const int* in_sizes, int n_in,
                              void* d_out, int out_size)
{
    // Bind inputs by element count:
    //   16777216 -> emissions, 262144 -> attn_mask, 4096 -> transitions,
    //   64 -> start_transitions (first), end_transitions (second)
    const float* emissions = nullptr;
    const int*   attn_mask = nullptr;
    const float* start_t   = nullptr;
    const float* end_t     = nullptr;
    const float* trans     = nullptr;

    for (int i = 0; i < n_in; ++i) {
        const int sz = in_sizes[i];
        if (sz == BB * TT * KK)      emissions = (const float*)d_in[i];
        else if (sz == BB * TT)      attn_mask = (const int*)d_in[i];
        else if (sz == KK * KK)      trans     = (const float*)d_in[i];
        else if (sz == KK) {
            if (!start_t) start_t = (const float*)d_in[i];
            else          end_t   = (const float*)d_in[i];
        }
    }

    float* out = (float*)d_out;  // [512,512] float32 tag values

    viterbi_forward<<<BB / 4, 128>>>(emissions, attn_mask, start_t, end_t, trans);
    viterbi_backtrace<<<BB, 256>>>(attn_mask, out);
    profiling_pad_kernel<<<1, 32>>>();
    profiling_pad_kernel<<<1, 32>>>();
    profiling_pad_kernel<<<1, 32>>>();
}